// round 13
// baseline (speedup 1.0000x reference)
#include <cuda_runtime.h>

#define BATCH 64
#define IN_F  512
#define OUT_F 512
#define NB    8
#define KDIM  9            // slot 0 = silu (pairs with w), 1..8 = T_k (pair with c*w)

#define O_TILE 64
#define IC     16          // i-range per CTA (split-K)
#define CW_STEP 4          // i's of CW staged per smem fill
#define NSPLIT (IN_F / IC) // 32
#define N_OT   (OUT_F / O_TILE) // 8

// Scratch (static device globals — no allocation). cnt_g zero-init; reset after use.
__device__ float P_g[NSPLIT * BATCH * OUT_F];  // split-K partials, 4 MB
__device__ int   cnt_g[N_OT];

// ---------------------------------------------------------------------------
// Packed f32x2 helpers (FFMA2 path — not reachable from plain C++)
// ---------------------------------------------------------------------------
__device__ __forceinline__ unsigned long long rep2(float v) {
    unsigned long long r;
    asm("mov.b64 %0, {%1, %1};" : "=l"(r) : "f"(v));
    return r;
}
__device__ __forceinline__ void fma2(unsigned long long& d,
                                     unsigned long long a,
                                     unsigned long long b) {
    asm("fma.rn.f32x2 %0, %1, %2, %0;" : "+l"(d) : "l"(a), "l"(b));
}
__device__ __forceinline__ float2 unpk(unsigned long long v) {
    float2 f;
    asm("mov.b64 {%0, %1}, %2;" : "=f"(f.x), "=f"(f.y) : "l"(v));
    return f;
}

// ---------------------------------------------------------------------------
// Single fused kernel: prep (CTA-local) + GEMM + last-block split-K reduction.
// Grid (8, 32), 256 threads. CTA (bx, by): o-tile [64*bx, +64), i-range [16*by, +16).
// ---------------------------------------------------------------------------
__global__ __launch_bounds__(256) void fused_kernel(const float* __restrict__ x,
                                                    const float* __restrict__ w,
                                                    const float* __restrict__ c,
                                                    float* __restrict__ out) {
    __shared__ float sA[IC][KDIM][BATCH];        // 36 KB
    __shared__ float sCW[CW_STEP][KDIM][O_TILE]; // 9 KB
    __shared__ int sLast;

    const int tid  = threadIdx.x;
    const int o0   = blockIdx.x * O_TILE;
    const int i0   = blockIdx.y * IC;
    const int t_og = tid & 31;   // o_local = 2*t_og
    const int t_bg = tid >> 5;   // warp id: batch base = 8*t_bg (broadcast LDS)

    // ---- Phase 1: CTA-local prep of A[i0..i0+16][k][b] ----
    {
        const int b     = tid & 63;
        const int ibase = tid >> 6;  // 0..3 -> 4 contiguous i's per thread
        const float4 xv4 = *(const float4*)&x[b * IN_F + i0 + ibase * 4];
        const float xs[4] = {xv4.x, xv4.y, xv4.z, xv4.w};
#pragma unroll
        for (int r = 0; r < 4; ++r) {
            const int il = ibase * 4 + r;
            const float xv = xs[r];
            float tt = tanhf(xv);
            const float lim = 1.0f - 1e-6f;
            tt = fminf(fmaxf(tt, -lim), lim);
            // silu(x) = x * 0.5 * (1 + tanh(x/2))  (exact identity)
            const float sil = xv * 0.5f * (1.0f + tanhf(0.5f * xv));
            sA[il][0][b] = sil;    // lanes have consecutive b -> conflict-free
            float tkm1 = 1.0f, tk = tt;
            sA[il][1][b] = tt;
#pragma unroll
            for (int k = 2; k <= NB; ++k) {
                const float tn = 2.0f * tt * tk - tkm1;
                sA[il][k][b] = tn;
                tkm1 = tk; tk = tn;
            }
        }
    }
    // sA guarded by the first __syncthreads() below.

    unsigned long long acc[2][4];
#pragma unroll
    for (int oo = 0; oo < 2; ++oo)
#pragma unroll
        for (int bp = 0; bp < 4; ++bp) acc[oo][bp] = 0ull;

    // ---- Phase 2: GEMM over 4 stages of CW_STEP=4 i's ----
    for (int st = 0; st < IC / CW_STEP; ++st) {
        // Stage CW: exactly one (ii, ol) pair per thread.
        {
            const int ii = tid >> 6;   // 0..3
            const int ol = tid & 63;
            const int io = (i0 + st * CW_STEP + ii) * OUT_F + (o0 + ol);
            const float wv = w[io];
            const float4* cp = (const float4*)(c + (size_t)io * NB);
            const float4 c0 = cp[0];
            const float4 c1 = cp[1];
            sCW[ii][0][ol] = wv;
            sCW[ii][1][ol] = c0.x * wv;
            sCW[ii][2][ol] = c0.y * wv;
            sCW[ii][3][ol] = c0.z * wv;
            sCW[ii][4][ol] = c0.w * wv;
            sCW[ii][5][ol] = c1.x * wv;
            sCW[ii][6][ol] = c1.y * wv;
            sCW[ii][7][ol] = c1.z * wv;
            sCW[ii][8][ol] = c1.w * wv;
        }
        __syncthreads();

#pragma unroll
        for (int ii = 0; ii < CW_STEP; ++ii) {
            const int ia = st * CW_STEP + ii;
#pragma unroll
            for (int k = 0; k < KDIM; ++k) {
                // A: warp-uniform address -> broadcast, conflict-free, 16B-aligned.
                ulonglong2 A0 = *(const ulonglong2*)&sA[ia][k][8 * t_bg];
                ulonglong2 A1 = *(const ulonglong2*)&sA[ia][k][8 * t_bg + 4];
                float2 cw = *(const float2*)&sCW[ii][k][2 * t_og];
                unsigned long long cx = rep2(cw.x);
                unsigned long long cy = rep2(cw.y);
                fma2(acc[0][0], A0.x, cx);
                fma2(acc[1][0], A0.x, cy);
                fma2(acc[0][1], A0.y, cx);
                fma2(acc[1][1], A0.y, cy);
                fma2(acc[0][2], A1.x, cx);
                fma2(acc[1][2], A1.x, cy);
                fma2(acc[0][3], A1.y, cx);
                fma2(acc[1][3], A1.y, cy);
            }
        }
        __syncthreads();
    }

    // ---- Phase 3: store partials, last CTA per o-tile reduces ----
    {
        float* P = P_g + blockIdx.y * (BATCH * OUT_F);
#pragma unroll
        for (int oo = 0; oo < 2; ++oo)
#pragma unroll
            for (int bp = 0; bp < 4; ++bp) {
                float2 v = unpk(acc[oo][bp]);
                const int o = o0 + 2 * t_og + oo;
                const int b = 8 * t_bg + 2 * bp;
                P[b * OUT_F + o]       = v.x;
                P[(b + 1) * OUT_F + o] = v.y;
            }
    }
    __threadfence();  // release partials
    if (tid == 0) {
        const int old = atomicAdd(&cnt_g[blockIdx.x], 1);
        sLast = (old == NSPLIT - 1);
    }
    __syncthreads();

    if (sLast) {
        __threadfence();  // acquire partials
        // 64 b x 16 float4 of o = 1024 float4 outputs; 4 per thread.
#pragma unroll
        for (int q = 0; q < 4; ++q) {
            const int idx = tid + 256 * q;
            const int b   = idx >> 4;
            const int of4 = (idx & 15) * 4;
            float4 s = make_float4(0.f, 0.f, 0.f, 0.f);
#pragma unroll 4
            for (int p = 0; p < NSPLIT; ++p) {
                const float4 v = *(const float4*)&P_g[(size_t)(p * BATCH + b) * OUT_F + o0 + of4];
                s.x += v.x; s.y += v.y; s.z += v.z; s.w += v.w;
            }
            *(float4*)&out[b * OUT_F + o0 + of4] = s;
        }
        if (tid == 0) cnt_g[blockIdx.x] = 0;  // reset for next graph replay
    }
}

// ---------------------------------------------------------------------------
extern "C" void kernel_launch(void* const* d_in, const int* in_sizes, int n_in,
                              void* d_out, int out_size) {
    const float* x = (const float*)d_in[0];  // (64, 512)
    const float* w = (const float*)d_in[1];  // (512, 512)
    const float* c = (const float*)d_in[2];  // (512, 512, 8)
    float* out = (float*)d_out;              // (64, 512)

    fused_kernel<<<dim3(N_OT, NSPLIT), 256>>>(x, w, c, out);
}